// round 13
// baseline (speedup 1.0000x reference)
#include <cuda_runtime.h>
#include <cuda_fp16.h>
#include <cstdint>

// ---------------------------------------------------------------------------
// Problem constants
// ---------------------------------------------------------------------------
#define B_   8
#define N_   1024
#define D_   512
#define C_   1024
#define Q_   8
#define M_   (B_ * N_)      // 8192 rows
#define D4_  (D_ / 4)

// Output layout (all float32): [quantized_out M*D][indices M*Q][losses Q]
#define OUT_IDX_OFF  ((size_t)M_ * D_)
#define OUT_LOSS_OFF ((size_t)M_ * D_ + (size_t)M_ * Q_)

// rescue margin (worst-case fp16-screen key error ~0.16)
#define DELTA 0.5f
#define CAP   64            // candidate list capacity per row

// ---------------------------------------------------------------------------
// Scratch (__device__ globals — allocation-free)
// ---------------------------------------------------------------------------
__device__ float g_residual[M_ * D_];
__device__ __half gA0[M_ * D_];            // fp16(residual)
__device__ __half gB0[Q_ * C_ * D_];       // fp16(codebooks)
__device__ float g_e2[Q_ * C_];
__device__ float g_loss[Q_];
__device__ unsigned long long g_cand[M_ * CAP];  // per-row candidate lists
__device__ int g_cnt[M_];                        // per-row candidate counts
__device__ int g_tile_cnt[M_ / 128];             // m-tile completion counters

// ---------------------------------------------------------------------------
// Arch-neutral PTX helpers (sm_80-level: cp.async / ldmatrix / mma.sync)
// ---------------------------------------------------------------------------
__device__ __forceinline__ uint32_t smem_to_u32(const void* p) {
    uint32_t a;
    asm("{ .reg .u64 t; cvta.to.shared.u64 t, %1; cvt.u32.u64 %0, t; }"
        : "=r"(a) : "l"(p));
    return a;
}
__device__ __forceinline__ void cp16(uint32_t dst, const void* src) {
    asm volatile("cp.async.cg.shared.global [%0], [%1], 16;"
                 :: "r"(dst), "l"(src));
}
#define CP_COMMIT() asm volatile("cp.async.commit_group;" ::: "memory")
#define CP_WAIT(n)  asm volatile("cp.async.wait_group %0;" :: "n"(n) : "memory")

__device__ __forceinline__ void ldm_x4(uint32_t* r, uint32_t addr) {
    asm volatile("ldmatrix.sync.aligned.m8n8.x4.shared.b16 {%0,%1,%2,%3}, [%4];"
                 : "=r"(r[0]), "=r"(r[1]), "=r"(r[2]), "=r"(r[3]) : "r"(addr));
}
__device__ __forceinline__ void mma16816(float* d, const uint32_t* a,
                                         uint32_t b0, uint32_t b1) {
    asm volatile(
        "mma.sync.aligned.m16n8k16.row.col.f32.f16.f16.f32 "
        "{%0,%1,%2,%3}, {%4,%5,%6,%7}, {%8,%9}, {%0,%1,%2,%3};"
        : "+f"(d[0]), "+f"(d[1]), "+f"(d[2]), "+f"(d[3])
        : "r"(a[0]), "r"(a[1]), "r"(a[2]), "r"(a[3]), "r"(b0), "r"(b1));
}

// monotone float -> uint transform (order-preserving)
__device__ __forceinline__ uint32_t ford(float f) {
    uint32_t u = __float_as_uint(f);
    return (u & 0x80000000u) ? ~u : (u | 0x80000000u);
}
__device__ __forceinline__ float funord(uint32_t u) {
    return __uint_as_float((u & 0x80000000u) ? (u ^ 0x80000000u) : ~u);
}

// warp-exact fp32 key for candidate `cand` against res4[4] (lane-strided row)
__device__ __forceinline__ float exact_key(const float4* res4,
                                           const float* cb, const float* e2q,
                                           int cand, int lane) {
    const float4* cr4 = (const float4*)(cb + (size_t)cand * D_);
    float dot = 0.f;
#pragma unroll
    for (int k = 0; k < 4; k++) {
        const float4 c4 = cr4[lane + 32 * k];
        const float4 r4 = res4[k];
        dot = fmaf(r4.x, c4.x, dot); dot = fmaf(r4.y, c4.y, dot);
        dot = fmaf(r4.z, c4.z, dot); dot = fmaf(r4.w, c4.w, dot);
    }
#pragma unroll
    for (int o = 16; o > 0; o >>= 1)
        dot += __shfl_xor_sync(0xffffffffu, dot, o);
    return e2q[cand] - 2.f * dot;
}

// ---------------------------------------------------------------------------
// init: residual = x, fp16 copy, zero loss + counters
// ---------------------------------------------------------------------------
__global__ void init_kernel(const float* __restrict__ x) {
    const int tid = blockIdx.x * blockDim.x + threadIdx.x;
    const int stride = gridDim.x * blockDim.x;
    for (int i = tid; i < M_ * D_; i += stride) {
        float v = x[i];
        g_residual[i] = v;
        gA0[i] = __float2half_rn(v);
    }
    for (int i = tid; i < M_; i += stride) g_cnt[i] = 0;
    if (tid < Q_) g_loss[tid] = 0.f;
    if (tid < M_ / 128) g_tile_cnt[tid] = 0;
}

// ---------------------------------------------------------------------------
// prep: e2 + fp16 copy for all 8 codebooks (one warp per row)
// ---------------------------------------------------------------------------
__global__ void prep_kernel(const float* __restrict__ cbs) {
    const int w = (blockIdx.x * blockDim.x + threadIdx.x) >> 5;
    const int lane = threadIdx.x & 31;
    if (w >= Q_ * C_) return;
    const float* row = cbs + (size_t)w * D_;
    __half* b0 = gB0 + (size_t)w * D_;
    float s = 0.f;
#pragma unroll
    for (int i = lane; i < D_; i += 32) {
        float v = row[i];
        s = fmaf(v, v, s);
        b0[i] = __float2half_rn(v);
    }
#pragma unroll
    for (int o = 16; o > 0; o >>= 1) s += __shfl_xor_sync(0xffffffffu, s, o);
    if (lane == 0) g_e2[w] = s;
}

// ---------------------------------------------------------------------------
// Fused screen + rerank + update.
// Phase 1 (all 512 CTAs): fp16 screen GEMM 128x128, keys -> smem, CTA-row min,
//   margin candidates appended to per-row global lists.
// Phase 2 (last CTA per m-tile via counter): exact fp32 winner from the lists,
//   residual update / loss / fp16 re-copy / index write for 128 rows.
// CRITICAL: __threadfence + __syncthreads between appends and counter arrival
// (all warps' appends must be globally visible before this CTA counts).
// ---------------------------------------------------------------------------
#define KCH    32
#define NCH    16              // 512 / 32
#define ROWB   80u             // 32 fp16 (64B) + 16B pad
#define TILEB  10240u          // 128 * 80
#define STAGEB 20480u          // A + B tiles
#define KEYROW 132             // padded keys row stride (floats)
#define OFF_E2 81920u
#define SMEM_BYTES 82432u

__global__ void __launch_bounds__(256, 2) fused_kernel(
    const float* __restrict__ cbs, float* __restrict__ idx_out, int q, int last) {
    extern __shared__ __align__(128) char smem[];
    __shared__ int s_last;
    __shared__ int scnt[128];
    __shared__ float wsum[8];
    const uint32_t sm = smem_to_u32(smem);

    const int t = threadIdx.x;
    const int lane = t & 31, wid = t >> 5;
    const int warp_m = (wid >> 2) * 64;     // 0 or 64
    const int warp_n = (wid & 3) * 32;      // 0..96
    const int bm0 = blockIdx.x * 128;
    const int c0  = blockIdx.y * 128;

    const __half* Bq0 = gB0 + (size_t)q * C_ * D_;
    float* e2s = (float*)(smem + OFF_E2);
    if (t < 128) e2s[t] = g_e2[q * C_ + c0 + t];

    const int lrow = t >> 1;
    const int lg   = t & 1;
    const __half* pa = gA0 + (size_t)(bm0 + lrow) * D_ + lg * 16;
    const __half* pb = Bq0 + (size_t)(c0 + lrow) * D_ + lg * 16;
    const uint32_t sdst = sm + lrow * ROWB + lg * 32;

    uint32_t a_off[4];
#pragma unroll
    for (int ma = 0; ma < 4; ma++)
        a_off[ma] = (uint32_t)((warp_m + ma * 16 + (lane & 15)) * ROWB +
                               (lane >> 4) * 16);
    uint32_t b_off[2];
#pragma unroll
    for (int p = 0; p < 2; p++)
        b_off[p] = (uint32_t)((warp_n + p * 16 + ((lane >> 4) << 3) + (lane & 7)) * ROWB +
                              ((lane >> 3) & 1) * 16);

    float acc[4][4][4];
#pragma unroll
    for (int i = 0; i < 4; i++)
#pragma unroll
        for (int j = 0; j < 4; j++)
#pragma unroll
            for (int e = 0; e < 4; e++) acc[i][j][e] = 0.f;

    auto issue_loads = [&](int kk) {
        const uint32_t buf = (uint32_t)(kk & 3) * STAGEB + sdst;
        const int col = kk * KCH;
        cp16(buf,              pa + col);
        cp16(buf + 16,         pa + col + 8);
        cp16(buf + TILEB,      pb + col);
        cp16(buf + TILEB + 16, pb + col + 8);
        CP_COMMIT();
    };

    issue_loads(0); issue_loads(1); issue_loads(2);

    for (int cc = 0; cc < NCH; cc++) {
        if (cc < NCH - 2)       CP_WAIT(2);
        else if (cc == NCH - 2) CP_WAIT(1);
        else                    CP_WAIT(0);
        __syncthreads();

        const uint32_t buf = sm + (uint32_t)(cc & 3) * STAGEB;
#pragma unroll
        for (int k = 0; k < 2; k++) {
            uint32_t a[4][4], bb[2][4];
#pragma unroll
            for (int ma = 0; ma < 4; ma++)
                ldm_x4(a[ma], buf + a_off[ma] + k * 32);
#pragma unroll
            for (int p = 0; p < 2; p++)
                ldm_x4(bb[p], buf + TILEB + b_off[p] + k * 32);
#pragma unroll
            for (int ma = 0; ma < 4; ma++)
#pragma unroll
                for (int nb = 0; nb < 4; nb++) {
                    const uint32_t* bp = bb[nb >> 1];
                    mma16816(acc[ma][nb], a[ma], bp[(nb & 1) * 2], bp[(nb & 1) * 2 + 1]);
                }
        }
        if (cc + 3 < NCH) issue_loads(cc + 3);
    }
    __syncthreads();   // all LDSM done before keys overwrite stage smem

    // ---- keys -> smem (acc dies here)
    const int g = lane >> 2, tg = lane & 3;
    float* keys = (float*)smem;              // reuse stage buffers, 128 x 132
#pragma unroll
    for (int ma = 0; ma < 4; ma++)
#pragma unroll
        for (int half = 0; half < 2; half++) {
            const int rloc = warp_m + ma * 16 + half * 8 + g;
#pragma unroll
            for (int nb = 0; nb < 4; nb++)
#pragma unroll
                for (int e2i = 0; e2i < 2; e2i++) {
                    const int cloc = warp_n + nb * 8 + tg * 2 + e2i;
                    keys[rloc * KEYROW + cloc] =
                        fmaf(-2.f, acc[ma][nb][half * 2 + e2i], e2s[cloc]);
                }
        }
    __syncthreads();

    // ---- scan: warp handles 16 rows; CTA-row min + margin appends
    for (int r = 0; r < 16; r++) {
        const int rloc = wid * 16 + r;
        float k4[4];
#pragma unroll
        for (int j = 0; j < 4; j++)
            k4[j] = keys[rloc * KEYROW + lane + 32 * j];
        float mn = fminf(fminf(k4[0], k4[1]), fminf(k4[2], k4[3]));
#pragma unroll
        for (int o = 16; o > 0; o >>= 1)
            mn = fminf(mn, __shfl_xor_sync(0xffffffffu, mn, o));
        const float th = mn + DELTA;
        const int row = bm0 + rloc;
#pragma unroll
        for (int j = 0; j < 4; j++) {
            if (k4[j] <= th) {
                const int cand = c0 + lane + 32 * j;
                const int slot = atomicAdd(&g_cnt[row], 1);
                if (slot < CAP)
                    g_cand[(size_t)row * CAP + slot] =
                        ((unsigned long long)ford(k4[j]) << 32) | (unsigned)cand;
            }
        }
    }

    // ---- RELEASE: all warps' appends globally visible BEFORE arrival
    __threadfence();
    __syncthreads();
    if (t == 0) s_last = (atomicAdd(&g_tile_cnt[blockIdx.x], 1) == 7);
    __syncthreads();
    if (!s_last) return;
    if (t == 0) g_tile_cnt[blockIdx.x] = 0;   // reset for next layer / replay
    __threadfence();

    if (t < 128) scnt[t] = atomicExch(&g_cnt[bm0 + t], 0);
    __syncthreads();

    const float* cb = cbs + (size_t)q * C_ * D_;
    const float* e2q = g_e2 + q * C_;
    float sq = 0.f;

    for (int r = 0; r < 16; r++) {
        const int rloc = wid * 16 + r;
        const int row = bm0 + rloc;
        const int cnt = scnt[rloc];

        const float4* rres = (const float4*)(g_residual + (size_t)row * D_);
        float4 res4[4];
#pragma unroll
        for (int k = 0; k < 4; k++) res4[k] = rres[lane + 32 * k];

        unsigned long long bestx = ~0ull;
        if (cnt <= CAP) {
            unsigned long long e0 =
                (lane < cnt) ? __ldcg(&g_cand[(size_t)row * CAP + lane]) : ~0ull;
            unsigned long long e1 =
                (lane + 32 < cnt) ? __ldcg(&g_cand[(size_t)row * CAP + lane + 32])
                                  : ~0ull;
            unsigned long long gm = (e0 < e1) ? e0 : e1;
#pragma unroll
            for (int o = 16; o > 0; o >>= 1) {
                unsigned long long other = __shfl_xor_sync(0xffffffffu, gm, o);
                if (other < gm) gm = other;
            }
            const float thresh = funord((uint32_t)(gm >> 32)) + DELTA;
#pragma unroll
            for (int half = 0; half < 2; half++) {
                const unsigned long long ee = half ? e1 : e0;
                const float ekey = funord((uint32_t)(ee >> 32));
                unsigned mask = __ballot_sync(0xffffffffu, ekey <= thresh);
                while (mask) {
                    const int b = __ffs(mask) - 1;
                    mask &= mask - 1;
                    const int cand =
                        (int)(__shfl_sync(0xffffffffu, ee, b) & 0xFFFFFFFFull);
                    const float ek = exact_key(res4, cb, e2q, cand, lane);
                    unsigned long long p =
                        ((unsigned long long)ford(ek) << 32) | (unsigned)cand;
                    if (p < bestx) bestx = p;
                }
            }
        } else {
            // overflow fallback: exact scan of all C candidates
            for (int cand = 0; cand < C_; cand++) {
                const float ek = exact_key(res4, cb, e2q, cand, lane);
                unsigned long long p =
                    ((unsigned long long)ford(ek) << 32) | (unsigned)cand;
                if (p < bestx) bestx = p;
            }
        }

        const int bidx = (int)(bestx & 0xFFFFFFFFull);
        if (lane == 0 && idx_out)
            idx_out[(size_t)row * Q_ + q] = (float)bidx;

        // update residual, loss, fp16 copy
        const float4* cw4 = (const float4*)(cb + (size_t)bidx * D_);
        float4* wres = (float4*)(g_residual + (size_t)row * D_);
#pragma unroll
        for (int k = 0; k < 4; k++) {
            const int j = lane + 32 * k;
            const float4 c4 = cw4[j];
            float4 rn;
            rn.x = res4[k].x - c4.x; rn.y = res4[k].y - c4.y;
            rn.z = res4[k].z - c4.z; rn.w = res4[k].w - c4.w;
            wres[j] = rn;
            sq = fmaf(rn.x, rn.x, sq); sq = fmaf(rn.y, rn.y, sq);
            sq = fmaf(rn.z, rn.z, sq); sq = fmaf(rn.w, rn.w, sq);
            if (!last) {
                __half2 h2a = __floats2half2_rn(rn.x, rn.y);
                __half2 h2b = __floats2half2_rn(rn.z, rn.w);
                *(uint2*)&gA0[(size_t)row * D_ + (size_t)j * 4] =
                    make_uint2(*(uint32_t*)&h2a, *(uint32_t*)&h2b);
            }
        }
    }
#pragma unroll
    for (int o = 16; o > 0; o >>= 1) sq += __shfl_xor_sync(0xffffffffu, sq, o);
    if (lane == 0) wsum[wid] = sq;
    __syncthreads();
    if (t == 0) {
        float s = 0.f;
#pragma unroll
        for (int w = 0; w < 8; w++) s += wsum[w];
        atomicAdd(&g_loss[q], s);
    }
}

// ---------------------------------------------------------------------------
// final: quantized_out = x - residual_final; write losses
// ---------------------------------------------------------------------------
__global__ void final_kernel(const float4* __restrict__ x,
                             float* __restrict__ out, int write_extra) {
    const int n4 = M_ * D_ / 4;
    float4* o4 = (float4*)out;
    const float4* r4 = (const float4*)g_residual;
    for (int i = blockIdx.x * blockDim.x + threadIdx.x; i < n4;
         i += gridDim.x * blockDim.x) {
        float4 xv = x[i], rv = r4[i];
        float4 ov;
        ov.x = xv.x - rv.x; ov.y = xv.y - rv.y;
        ov.z = xv.z - rv.z; ov.w = xv.w - rv.w;
        o4[i] = ov;
    }
    if (write_extra && blockIdx.x == 0 && threadIdx.x < Q_)
        out[OUT_LOSS_OFF + threadIdx.x] =
            g_loss[threadIdx.x] * (1.0f / ((float)M_ * (float)D_));
}

// ---------------------------------------------------------------------------
extern "C" void kernel_launch(void* const* d_in, const int* in_sizes, int n_in,
                              void* d_out, int out_size) {
    const float* x   = (const float*)d_in[0];
    const float* cbs = (const float*)d_in[1];
    float* out = (float*)d_out;

    const int full = (int)(OUT_LOSS_OFF + Q_);
    const int write_extra = (out_size >= full) ? 1 : 0;
    float* idx_out = write_extra ? out + OUT_IDX_OFF : nullptr;

    static int attr_done = 0;
    if (!attr_done) {
        cudaFuncSetAttribute(fused_kernel,
                             cudaFuncAttributeMaxDynamicSharedMemorySize,
                             SMEM_BYTES);
        attr_done = 1;
    }

    init_kernel<<<1024, 256>>>(x);
    prep_kernel<<<(Q_ * C_ * 32) / 256, 256>>>(cbs);
    for (int q = 0; q < Q_; q++)
        fused_kernel<<<dim3(64, 8), 256, SMEM_BYTES>>>(cbs, idx_out, q,
                                                       q == Q_ - 1);
    final_kernel<<<512, 256>>>((const float4*)x, out, write_extra);
}

// round 14
// speedup vs baseline: 1.4688x; 1.4688x over previous
#include <cuda_runtime.h>
#include <cuda_fp16.h>
#include <cstdint>

// ---------------------------------------------------------------------------
// Problem constants
// ---------------------------------------------------------------------------
#define B_   8
#define N_   1024
#define D_   512
#define C_   1024
#define Q_   8
#define M_   (B_ * N_)      // 8192 rows
#define D4_  (D_ / 4)

// Output layout (all float32): [quantized_out M*D][indices M*Q][losses Q]
#define OUT_IDX_OFF  ((size_t)M_ * D_)
#define OUT_LOSS_OFF ((size_t)M_ * D_ + (size_t)M_ * Q_)

// rescue margin: screen fp16-dot error (~0.16) + fp16 storage error (~0.13)
#define DELTA 0.75f

// ---------------------------------------------------------------------------
// Scratch (__device__ globals — allocation-free)
// ---------------------------------------------------------------------------
__device__ float g_residual[M_ * D_];
__device__ __half gA0[M_ * D_];            // fp16(residual)
__device__ __half gB0[Q_ * C_ * D_];       // fp16(codebooks)
__device__ float g_e2[Q_ * C_];
__device__ float g_loss[Q_];
__device__ __half g_dots[M_ * C_];         // fp16(-2*dot) matrix (16.7 MB)

// ---------------------------------------------------------------------------
// Arch-neutral PTX helpers (sm_80-level: cp.async / ldmatrix / mma.sync)
// ---------------------------------------------------------------------------
__device__ __forceinline__ uint32_t smem_to_u32(const void* p) {
    uint32_t a;
    asm("{ .reg .u64 t; cvta.to.shared.u64 t, %1; cvt.u32.u64 %0, t; }"
        : "=r"(a) : "l"(p));
    return a;
}
__device__ __forceinline__ void cp16(uint32_t dst, const void* src) {
    asm volatile("cp.async.cg.shared.global [%0], [%1], 16;"
                 :: "r"(dst), "l"(src));
}
#define CP_COMMIT() asm volatile("cp.async.commit_group;" ::: "memory")
#define CP_WAIT(n)  asm volatile("cp.async.wait_group %0;" :: "n"(n) : "memory")

__device__ __forceinline__ void ldm_x4(uint32_t* r, uint32_t addr) {
    asm volatile("ldmatrix.sync.aligned.m8n8.x4.shared.b16 {%0,%1,%2,%3}, [%4];"
                 : "=r"(r[0]), "=r"(r[1]), "=r"(r[2]), "=r"(r[3]) : "r"(addr));
}
__device__ __forceinline__ void mma16816(float* d, const uint32_t* a,
                                         uint32_t b0, uint32_t b1) {
    asm volatile(
        "mma.sync.aligned.m16n8k16.row.col.f32.f16.f16.f32 "
        "{%0,%1,%2,%3}, {%4,%5,%6,%7}, {%8,%9}, {%0,%1,%2,%3};"
        : "+f"(d[0]), "+f"(d[1]), "+f"(d[2]), "+f"(d[3])
        : "r"(a[0]), "r"(a[1]), "r"(a[2]), "r"(a[3]), "r"(b0), "r"(b1));
}

// monotone float -> uint transform (order-preserving, for packed min)
__device__ __forceinline__ uint32_t ford(float f) {
    uint32_t u = __float_as_uint(f);
    return (u & 0x80000000u) ? ~u : (u | 0x80000000u);
}
__device__ __forceinline__ float funord(uint32_t u) {
    return __uint_as_float((u & 0x80000000u) ? (u ^ 0x80000000u) : ~u);
}

// ---------------------------------------------------------------------------
// init: residual = x, fp16 copy, zero loss
// ---------------------------------------------------------------------------
__global__ void init_kernel(const float* __restrict__ x) {
    const int tid = blockIdx.x * blockDim.x + threadIdx.x;
    const int stride = gridDim.x * blockDim.x;
    for (int i = tid; i < M_ * D_; i += stride) {
        float v = x[i];
        g_residual[i] = v;
        gA0[i] = __float2half_rn(v);
    }
    if (tid < Q_) g_loss[tid] = 0.f;
}

// ---------------------------------------------------------------------------
// prep: e2 + fp16 copy for all 8 codebooks (one warp per row)
// ---------------------------------------------------------------------------
__global__ void prep_kernel(const float* __restrict__ cbs) {
    const int w = (blockIdx.x * blockDim.x + threadIdx.x) >> 5;
    const int lane = threadIdx.x & 31;
    if (w >= Q_ * C_) return;
    const float* row = cbs + (size_t)w * D_;
    __half* b0 = gB0 + (size_t)w * D_;
    float s = 0.f;
#pragma unroll
    for (int i = lane; i < D_; i += 32) {
        float v = row[i];
        s = fmaf(v, v, s);
        b0[i] = __float2half_rn(v);
    }
#pragma unroll
    for (int o = 16; o > 0; o >>= 1) s += __shfl_xor_sync(0xffffffffu, s, o);
    if (lane == 0) g_e2[w] = s;
}

// ---------------------------------------------------------------------------
// Screen GEMM: single fp16 product, fp32 accumulate. CTA 128x128, K=512,
// 8 warps @ 64x32, 4-stage cp.async pipeline, k-chunk 32.
// Epilogue writes fp16(-2*dot) to g_dots (half the R8 fp32-keys traffic).
// ---------------------------------------------------------------------------
#define KCH    32
#define NCH    16              // 512 / 32
#define ROWB   80u             // 32 fp16 (64B) + 16B pad
#define TILEB  10240u          // 128 * 80
#define STAGEB 20480u          // A + B tiles
#define SMEM_BYTES 81920u

__global__ void __launch_bounds__(256, 2) screen_kernel(int q) {
    extern __shared__ __align__(128) char smem[];
    const uint32_t sm = smem_to_u32(smem);

    const int t = threadIdx.x;
    const int lane = t & 31, wid = t >> 5;
    const int warp_m = (wid >> 2) * 64;     // 0 or 64
    const int warp_n = (wid & 3) * 32;      // 0..96
    const int bm0 = blockIdx.x * 128;
    const int c0  = blockIdx.y * 128;

    const __half* Bq0 = gB0 + (size_t)q * C_ * D_;

    // loader mapping: row = t>>1 (128 rows), granule g = t&1 (32B half-row)
    const int lrow = t >> 1;
    const int lg   = t & 1;
    const __half* pa = gA0 + (size_t)(bm0 + lrow) * D_ + lg * 16;
    const __half* pb = Bq0 + (size_t)(c0 + lrow) * D_ + lg * 16;
    const uint32_t sdst = sm + lrow * ROWB + lg * 32;

    uint32_t a_off[4];
#pragma unroll
    for (int ma = 0; ma < 4; ma++)
        a_off[ma] = (uint32_t)((warp_m + ma * 16 + (lane & 15)) * ROWB +
                               (lane >> 4) * 16);
    uint32_t b_off[2];
#pragma unroll
    for (int p = 0; p < 2; p++)
        b_off[p] = (uint32_t)((warp_n + p * 16 + ((lane >> 4) << 3) + (lane & 7)) * ROWB +
                              ((lane >> 3) & 1) * 16);

    float acc[4][4][4];
#pragma unroll
    for (int i = 0; i < 4; i++)
#pragma unroll
        for (int j = 0; j < 4; j++)
#pragma unroll
            for (int e = 0; e < 4; e++) acc[i][j][e] = 0.f;

    auto issue_loads = [&](int kk) {
        const uint32_t buf = (uint32_t)(kk & 3) * STAGEB + sdst;
        const int col = kk * KCH;
        cp16(buf,              pa + col);
        cp16(buf + 16,         pa + col + 8);
        cp16(buf + TILEB,      pb + col);
        cp16(buf + TILEB + 16, pb + col + 8);
        CP_COMMIT();
    };

    issue_loads(0); issue_loads(1); issue_loads(2);

    for (int cc = 0; cc < NCH; cc++) {
        if (cc < NCH - 2)       CP_WAIT(2);
        else if (cc == NCH - 2) CP_WAIT(1);
        else                    CP_WAIT(0);
        __syncthreads();

        const uint32_t buf = sm + (uint32_t)(cc & 3) * STAGEB;
#pragma unroll
        for (int k = 0; k < 2; k++) {           // two k=16 steps (bytes +0/+32)
            uint32_t a[4][4], bb[2][4];
#pragma unroll
            for (int ma = 0; ma < 4; ma++)
                ldm_x4(a[ma], buf + a_off[ma] + k * 32);
#pragma unroll
            for (int p = 0; p < 2; p++)
                ldm_x4(bb[p], buf + TILEB + b_off[p] + k * 32);
#pragma unroll
            for (int ma = 0; ma < 4; ma++)
#pragma unroll
                for (int nb = 0; nb < 4; nb++) {
                    const uint32_t* bp = bb[nb >> 1];
                    mma16816(acc[ma][nb], a[ma], bp[(nb & 1) * 2], bp[(nb & 1) * 2 + 1]);
                }
        }
        if (cc + 3 < NCH) issue_loads(cc + 3);
        __syncthreads();
    }

    // epilogue: write fp16(-2*dot) pairs (half2 stores)
    const int g = lane >> 2, tg = lane & 3;
#pragma unroll
    for (int ma = 0; ma < 4; ma++) {
#pragma unroll
        for (int half = 0; half < 2; half++) {
            const int row = bm0 + warp_m + ma * 16 + half * 8 + g;
            __half* krow = g_dots + (size_t)row * C_ + c0 + warp_n;
#pragma unroll
            for (int nb = 0; nb < 4; nb++) {
                __half2 hv = __floats2half2_rn(
                    -2.f * acc[ma][nb][half * 2 + 0],
                    -2.f * acc[ma][nb][half * 2 + 1]);
                *(__half2*)(krow + nb * 8 + tg * 2) = hv;
            }
        }
    }
}

// ---------------------------------------------------------------------------
// rerank + update: one warp per row. Scan approx keys (e2 + fp16 dots),
// exact fp32 re-rank of candidates within DELTA of the row min, then
// residual update / loss / fp16 re-copy / index write.
// ---------------------------------------------------------------------------
__global__ void __launch_bounds__(256) rerank_kernel(
    const float* __restrict__ cbs, float* __restrict__ idx_out, int q, int last) {
    const int lane = threadIdx.x & 31, wid = threadIdx.x >> 5;
    const int row = blockIdx.x * 8 + wid;
    const float* cb = cbs + (size_t)q * C_ * D_;
    __shared__ float wsum[8];
    __shared__ float e2s[C_];

    // cooperative e2 load (shared by all 8 rows of this block)
    {
        const float* e2q = g_e2 + q * C_;
#pragma unroll
        for (int i = 0; i < C_ / 256; i++)
            e2s[threadIdx.x + 256 * i] = e2q[threadIdx.x + 256 * i];
    }
    __syncthreads();

    // residual row, lane-strided
    float res[16];
#pragma unroll
    for (int k = 0; k < 16; k++)
        res[k] = g_residual[(size_t)row * D_ + lane + 32 * k];

    // load this lane's 32 approx keys: e2 + fp16(-2*dot)
    const __half* drow = g_dots + (size_t)row * C_;
    float keys[32];
#pragma unroll
    for (int kp = 0; kp < 32; kp++)
        keys[kp] = e2s[kp * 32 + lane] + __half2float(drow[kp * 32 + lane]);

    // packed min over the row (tie -> smallest index)
    unsigned long long pk = ~0ull;
#pragma unroll
    for (int kp = 0; kp < 32; kp++) {
        unsigned long long p =
            ((unsigned long long)ford(keys[kp]) << 32) | (unsigned)(kp * 32 + lane);
        if (p < pk) pk = p;
    }
#pragma unroll
    for (int o = 16; o > 0; o >>= 1) {
        unsigned long long other = __shfl_xor_sync(0xffffffffu, pk, o);
        if (other < pk) pk = other;
    }
    const float thresh = funord((uint32_t)(pk >> 32)) + DELTA;

    // exact re-rank of margin candidates
    unsigned long long bestx = ~0ull;
#pragma unroll
    for (int kp = 0; kp < 32; kp++) {
        unsigned mask = __ballot_sync(0xffffffffu, keys[kp] <= thresh);
        while (mask) {
            const int b = __ffs(mask) - 1;
            mask &= mask - 1;
            const int cand = kp * 32 + b;
            const float* cr = cb + (size_t)cand * D_;
            float dot = 0.f;
#pragma unroll
            for (int k = 0; k < 16; k++)
                dot = fmaf(res[k], cr[lane + 32 * k], dot);
#pragma unroll
            for (int o = 16; o > 0; o >>= 1)
                dot += __shfl_xor_sync(0xffffffffu, dot, o);
            const float ek = e2s[cand] - 2.f * dot;
            unsigned long long p =
                ((unsigned long long)ford(ek) << 32) | (unsigned)cand;
            if (p < bestx) bestx = p;
        }
    }
    const int bidx = (int)(bestx & 0xFFFFFFFFull);
    if (lane == 0 && idx_out)
        idx_out[(size_t)row * Q_ + q] = (float)bidx;

    // update residual, loss, fp16 copy
    const float* cw = cb + (size_t)bidx * D_;
    float sq = 0.f;
#pragma unroll
    for (int k = 0; k < 16; k++) {
        const int j = lane + 32 * k;
        float rn = res[k] - cw[j];
        g_residual[(size_t)row * D_ + j] = rn;
        sq = fmaf(rn, rn, sq);
        if (!last) gA0[(size_t)row * D_ + j] = __float2half_rn(rn);
    }
#pragma unroll
    for (int o = 16; o > 0; o >>= 1) sq += __shfl_xor_sync(0xffffffffu, sq, o);
    if (lane == 0) wsum[wid] = sq;
    __syncthreads();
    if (threadIdx.x == 0) {
        float s = 0.f;
#pragma unroll
        for (int w = 0; w < 8; w++) s += wsum[w];
        atomicAdd(&g_loss[q], s);
    }
}

// ---------------------------------------------------------------------------
// final: quantized_out = x - residual_final; write losses
// ---------------------------------------------------------------------------
__global__ void final_kernel(const float4* __restrict__ x,
                             float* __restrict__ out, int write_extra) {
    const int n4 = M_ * D_ / 4;
    float4* o4 = (float4*)out;
    const float4* r4 = (const float4*)g_residual;
    for (int i = blockIdx.x * blockDim.x + threadIdx.x; i < n4;
         i += gridDim.x * blockDim.x) {
        float4 xv = x[i], rv = r4[i];
        float4 ov;
        ov.x = xv.x - rv.x; ov.y = xv.y - rv.y;
        ov.z = xv.z - rv.z; ov.w = xv.w - rv.w;
        o4[i] = ov;
    }
    if (write_extra && blockIdx.x == 0 && threadIdx.x < Q_)
        out[OUT_LOSS_OFF + threadIdx.x] =
            g_loss[threadIdx.x] * (1.0f / ((float)M_ * (float)D_));
}

// ---------------------------------------------------------------------------
extern "C" void kernel_launch(void* const* d_in, const int* in_sizes, int n_in,
                              void* d_out, int out_size) {
    const float* x   = (const float*)d_in[0];
    const float* cbs = (const float*)d_in[1];
    float* out = (float*)d_out;

    const int full = (int)(OUT_LOSS_OFF + Q_);
    const int write_extra = (out_size >= full) ? 1 : 0;
    float* idx_out = write_extra ? out + OUT_IDX_OFF : nullptr;

    static int attr_done = 0;
    if (!attr_done) {
        cudaFuncSetAttribute(screen_kernel,
                             cudaFuncAttributeMaxDynamicSharedMemorySize,
                             SMEM_BYTES);
        attr_done = 1;
    }

    init_kernel<<<1024, 256>>>(x);
    prep_kernel<<<(Q_ * C_ * 32) / 256, 256>>>(cbs);
    for (int q = 0; q < Q_; q++) {
        screen_kernel<<<dim3(64, 8), 256, SMEM_BYTES>>>(q);
        rerank_kernel<<<M_ / 8, 256>>>(cbs, idx_out, q, q == Q_ - 1);
    }
    final_kernel<<<512, 256>>>((const float4*)x, out, write_extra);
}